// round 1
// baseline (speedup 1.0000x reference)
#include <cuda_runtime.h>

#define NPTS  100000
#define BATCH 16
#define MNB   9
#define PTS_PER_BLK2 16
#define NBLK2 (NPTS / PTS_PER_BLK2)   /* 6250, exact */
#define TP 64                          /* points per transpose tile */

// Scratch: d = gt - pr, transposed to (n, c, b) layout: g_dt[n*48 + c*16 + b]
__device__ float g_dt[NPTS * 48];
__device__ float g_partial[NBLK2];

// ---------------------------------------------------------------------------
// Kernel 1: diff + transpose (B,N,3) -> (N,3,B), smem-tiled, coalesced both ways
// ---------------------------------------------------------------------------
__global__ void k_diff(const float* __restrict__ gt, const float* __restrict__ pr) {
    __shared__ float s[TP * 48];
    int n0 = blockIdx.x * TP;

    // Load: i walks (b, point, c) with (point,c) contiguous per b -> coalesced reads
    for (int i = threadIdx.x; i < TP * 48; i += blockDim.x) {
        int b = i / (TP * 3);
        int r = i % (TP * 3);
        int p = r / 3;
        int c = r % 3;
        int n = n0 + p;
        float v = 0.0f;
        if (n < NPTS) {
            int gidx = b * (NPTS * 3) + n * 3 + c;
            v = gt[gidx] - pr[gidx];
        }
        s[p * 48 + c * 16 + b] = v;
    }
    __syncthreads();

    // Store: output region [n0*48, n0*48 + valid*48) is contiguous
    int valid = NPTS - n0;
    if (valid > TP) valid = TP;
    int total = valid * 48;
    int base = n0 * 48;
    for (int j = threadIdx.x; j < total; j += blockDim.x)
        g_dt[base + j] = s[j];
}

// ---------------------------------------------------------------------------
// Kernel 2: laplacian diff + |.| accumulation.
// 16 lanes = 16 batches handle one point; block = 256 threads = 16 points.
// Deterministic per-block partial sums (no float atomics).
// ---------------------------------------------------------------------------
__global__ void k_lap(const int* __restrict__ nb, const float* __restrict__ num) {
    int tid  = threadIdx.x;
    int lane = tid & 15;          // batch index
    int n    = blockIdx.x * PTS_PER_BLK2 + (tid >> 4);   // always < NPTS (exact grid)

    // lanes 0..8 of each 16-lane group load the neighbor row
    int myid = (lane < MNB) ? nb[n * MNB + lane] : 0;
    float wnum = num[n];

    const unsigned FULL = 0xFFFFFFFFu;
    int id0 = __shfl_sync(FULL, myid, 0, 16);
    int id1 = __shfl_sync(FULL, myid, 1, 16);
    int id2 = __shfl_sync(FULL, myid, 2, 16);
    int id3 = __shfl_sync(FULL, myid, 3, 16);
    int id4 = __shfl_sync(FULL, myid, 4, 16);
    int id5 = __shfl_sync(FULL, myid, 5, 16);
    int id6 = __shfl_sync(FULL, myid, 6, 16);
    int id7 = __shfl_sync(FULL, myid, 7, 16);
    int id8 = __shfl_sync(FULL, myid, 8, 16);

    const float* pc = g_dt + (size_t)id0 * 48 + lane;
    float c0 = pc[0]  * wnum;
    float c1 = pc[16] * wnum;
    float c2 = pc[32] * wnum;

#define SUB_NB(idj)                                                \
    if ((idj) < NPTS) {                                            \
        const float* p_ = g_dt + (size_t)(idj) * 48 + lane;        \
        c0 -= p_[0]; c1 -= p_[16]; c2 -= p_[32];                   \
    }
    SUB_NB(id1) SUB_NB(id2) SUB_NB(id3) SUB_NB(id4)
    SUB_NB(id5) SUB_NB(id6) SUB_NB(id7) SUB_NB(id8)
#undef SUB_NB

    float acc = fabsf(c0) + fabsf(c1) + fabsf(c2);

    // warp reduce (fixed order -> deterministic)
    #pragma unroll
    for (int off = 16; off > 0; off >>= 1)
        acc += __shfl_down_sync(FULL, acc, off);

    __shared__ float ws[8];
    if ((tid & 31) == 0) ws[tid >> 5] = acc;
    __syncthreads();
    if (tid < 8) {
        float v = ws[tid];
        #pragma unroll
        for (int off = 4; off > 0; off >>= 1)
            v += __shfl_down_sync(0xFFu, v, off);
        if (tid == 0) g_partial[blockIdx.x] = v;
    }
}

// ---------------------------------------------------------------------------
// Kernel 3: deterministic final reduction + mean
// ---------------------------------------------------------------------------
__global__ void k_reduce(float* __restrict__ out) {
    __shared__ float s[1024];
    float v = 0.0f;
    for (int i = threadIdx.x; i < NBLK2; i += 1024)
        v += g_partial[i];
    s[threadIdx.x] = v;
    __syncthreads();
    #pragma unroll
    for (int off = 512; off > 0; off >>= 1) {
        if (threadIdx.x < off) s[threadIdx.x] += s[threadIdx.x + off];
        __syncthreads();
    }
    if (threadIdx.x == 0)
        out[0] = s[0] * (1.0f / (float)(BATCH * NPTS * 3));
}

// ---------------------------------------------------------------------------
extern "C" void kernel_launch(void* const* d_in, const int* in_sizes, int n_in,
                              void* d_out, int out_size) {
    const float* gt  = (const float*)d_in[0];   // gt_pc        (B,N,3) f32
    const float* pr  = (const float*)d_in[1];   // predict_pc   (B,N,3) f32
    const int*   nb  = (const int*)  d_in[2];   // neighbor ids (N,9)   i32
    const float* num = (const float*)d_in[3];   // neighbor_num (N,)    f32
    float* out = (float*)d_out;

    int nblk1 = (NPTS + TP - 1) / TP;           // 1563
    k_diff  <<<nblk1, 256>>>(gt, pr);
    k_lap   <<<NBLK2, 256>>>(nb, num);
    k_reduce<<<1, 1024>>>(out);
}